// round 1
// baseline (speedup 1.0000x reference)
#include <cuda_runtime.h>
#include <cuda_bf16.h>
#include <math.h>

// Problem constants
#define Hn   512
#define DHn  2048          // 4*H
#define Bn   32
#define Sn   2048
#define Mrows (Sn * Bn)    // 65536 rows of the big GEMM

// GEMM tiling
#define BM 128
#define BN 128
#define BK 8
#define NBLK (Hn / BN)     // 4 column blocks

// Scratch (device globals: no allocation allowed in kernel_launch)
__device__ float g_hpart[Bn * Hn];             // 32x512
__device__ float g_partial[NBLK * Mrows];      // 4 x 65536 partial v-dots

// ---------------------------------------------------------------------------
// Kernel 1: hpart[b][d] = hidden[b] @ W_h[:,d] + b_attn[d]
// grid 64 blocks x 256 threads; each thread one (b,d)
// ---------------------------------------------------------------------------
__global__ __launch_bounds__(256) void hpart_kernel(
    const float* __restrict__ hidden,      // (32, 2048)
    const float* __restrict__ W_attn,      // (2560, 512); W_h = first 2048 rows
    const float* __restrict__ b_attn)      // (512,)
{
    int b = blockIdx.x >> 1;
    int d = ((blockIdx.x & 1) << 8) + threadIdx.x;
    const float* __restrict__ hrow = hidden + b * DHn;
    float acc = b_attn[d];
#pragma unroll 8
    for (int k = 0; k < DHn; k++) {
        acc = fmaf(hrow[k], W_attn[k * Hn + d], acc);
    }
    g_hpart[b * Hn + d] = acc;
}

// ---------------------------------------------------------------------------
// Kernel 2: fused GEMM + tanh + v-dot
//   rows r = s*32 + b (contiguous in encoder_outputs), cols d
//   C[r][d] = enc_row[r] @ W_e[:,d]
//   partial[blockN][r] = sum_{d in col tile} v[d] * tanh(C[r][d] + hpart[b][d])
// 128x128 tile, BK=8, 256 threads, 8x8 per-thread microtile.
// ---------------------------------------------------------------------------
__global__ __launch_bounds__(256) void fused_gemm_kernel(
    const float* __restrict__ enc,         // (S*B, 512) row-major
    const float* __restrict__ W_attn,      // W_e = rows [2048, 2560)
    const float* __restrict__ v)           // (512,)
{
    __shared__ float As[BK][BM];
    __shared__ float Bs[BK][BN];
    __shared__ float red[BM][17];          // padded reduce buffer

    const float* __restrict__ Bm = W_attn + (size_t)DHn * Hn;  // W_e
    const int rowbase = blockIdx.x * BM;
    const int colbase = blockIdx.y * BN;
    const int tid = threadIdx.x;

    // A tile load mapping: 256 float4 per 128x8 tile
    const int arow = tid >> 1;             // 0..127
    const int acol = (tid & 1) << 2;       // 0 or 4
    // B tile load mapping: 8x128 tile = 256 float4
    const int brow = tid >> 5;             // 0..7
    const int bcol = (tid & 31) << 2;      // 0..124

    const int ty = tid >> 4;               // 0..15 -> row group
    const int tx = tid & 15;               // 0..15 -> col group

    float acc[8][8];
#pragma unroll
    for (int i = 0; i < 8; i++)
#pragma unroll
        for (int j = 0; j < 8; j++) acc[i][j] = 0.0f;

    const float* __restrict__ Aptr = enc + (size_t)rowbase * Hn;

    for (int k0 = 0; k0 < Hn; k0 += BK) {
        float4 a4 = *(const float4*)(Aptr + (size_t)arow * Hn + k0 + acol);
        As[acol + 0][arow] = a4.x;
        As[acol + 1][arow] = a4.y;
        As[acol + 2][arow] = a4.z;
        As[acol + 3][arow] = a4.w;
        float4 b4 = *(const float4*)(Bm + (size_t)(k0 + brow) * Hn + colbase + bcol);
        *(float4*)&Bs[brow][bcol] = b4;
        __syncthreads();

#pragma unroll
        for (int k = 0; k < BK; k++) {
            float4 rm0 = *(const float4*)&As[k][ty * 8];
            float4 rm1 = *(const float4*)&As[k][ty * 8 + 4];
            float4 rn0 = *(const float4*)&Bs[k][tx * 8];
            float4 rn1 = *(const float4*)&Bs[k][tx * 8 + 4];
            float rm[8] = {rm0.x, rm0.y, rm0.z, rm0.w, rm1.x, rm1.y, rm1.z, rm1.w};
            float rn[8] = {rn0.x, rn0.y, rn0.z, rn0.w, rn1.x, rn1.y, rn1.z, rn1.w};
#pragma unroll
            for (int i = 0; i < 8; i++)
#pragma unroll
                for (int j = 0; j < 8; j++)
                    acc[i][j] = fmaf(rm[i], rn[j], acc[i][j]);
        }
        __syncthreads();
    }

    // Epilogue: + hpart, tanh, weighted column sum (partial over this col tile)
    float vloc[8];
#pragma unroll
    for (int j = 0; j < 8; j++) vloc[j] = v[colbase + tx * 8 + j];

#pragma unroll
    for (int i = 0; i < 8; i++) {
        const int r = rowbase + ty * 8 + i;
        const int b = r & (Bn - 1);
        const float* __restrict__ hp = g_hpart + b * Hn + colbase + tx * 8;
        float p = 0.0f;
#pragma unroll
        for (int j = 0; j < 8; j++) {
            float e = tanhf(acc[i][j] + hp[j]);
            p = fmaf(e, vloc[j], p);
        }
        red[ty * 8 + i][tx] = p;
    }
    __syncthreads();

    if (tid < BM) {
        float s = 0.0f;
#pragma unroll
        for (int j = 0; j < 16; j++) s += red[tid][j];
        g_partial[blockIdx.y * Mrows + rowbase + tid] = s;
    }
}

// ---------------------------------------------------------------------------
// Kernel 3: sum the 4 column-block partials, softmax over s per batch b
// one block per b (32 blocks), 256 threads
// ---------------------------------------------------------------------------
__global__ __launch_bounds__(256) void softmax_kernel(float* __restrict__ out)
{
    const int b = blockIdx.x;
    const int tid = threadIdx.x;
    __shared__ float logits[Sn];
    __shared__ float redbuf[256];

    for (int s = tid; s < Sn; s += 256) {
        float t = 0.0f;
#pragma unroll
        for (int j = 0; j < NBLK; j++) t += g_partial[j * Mrows + s * Bn + b];
        logits[s] = t;
    }
    __syncthreads();

    float m = -INFINITY;
    for (int s = tid; s < Sn; s += 256) m = fmaxf(m, logits[s]);
    redbuf[tid] = m;
    __syncthreads();
    for (int off = 128; off > 0; off >>= 1) {
        if (tid < off) redbuf[tid] = fmaxf(redbuf[tid], redbuf[tid + off]);
        __syncthreads();
    }
    m = redbuf[0];
    __syncthreads();

    float sum = 0.0f;
    for (int s = tid; s < Sn; s += 256) {
        float e = expf(logits[s] - m);
        logits[s] = e;
        sum += e;
    }
    redbuf[tid] = sum;
    __syncthreads();
    for (int off = 128; off > 0; off >>= 1) {
        if (tid < off) redbuf[tid] += redbuf[tid + off];
        __syncthreads();
    }
    const float inv = 1.0f / redbuf[0];
    __syncthreads();

    for (int s = tid; s < Sn; s += 256) {
        out[b * Sn + s] = logits[s] * inv;
    }
}

// ---------------------------------------------------------------------------
// Launch
// ---------------------------------------------------------------------------
extern "C" void kernel_launch(void* const* d_in, const int* in_sizes, int n_in,
                              void* d_out, int out_size)
{
    const float* hidden = (const float*)d_in[0];   // (32, 2048)
    const float* enc    = (const float*)d_in[1];   // (2048, 32, 512)
    const float* W_attn = (const float*)d_in[2];   // (2560, 512)
    const float* b_attn = (const float*)d_in[3];   // (512,)
    const float* v      = (const float*)d_in[4];   // (512,)
    float* out = (float*)d_out;                    // (32, 2048)

    hpart_kernel<<<64, 256>>>(hidden, W_attn, b_attn);

    dim3 grid(Mrows / BM, NBLK);                   // (512, 4)
    fused_gemm_kernel<<<grid, 256>>>(enc, W_attn, v);

    softmax_kernel<<<Bn, 256>>>(out);
}

// round 3
// speedup vs baseline: 2.6056x; 2.6056x over previous
#include <cuda_runtime.h>
#include <cuda_bf16.h>
#include <math.h>
#include <stdint.h>

// ---------------------------------------------------------------------------
// Problem constants
// ---------------------------------------------------------------------------
#define Hn   512
#define DHn  2048
#define Bn   32
#define Sn   2048
#define Mrows (Sn * Bn)       // 65536

// GEMM tiling
#define TM 128
#define TN 128
#define KC 64
#define NCHUNK (Hn / KC)      // 8
#define NBLK (Hn / TN)        // 4

// smem stage layout: Ahi(16K) Alo(16K) Bhi(16K) Blo(16K) = 64KB/stage, 2 stages
#define STG_BYTES 65536
#define OFF_AHI 0
#define OFF_ALO 16384
#define OFF_BHI 32768
#define OFF_BLO 49152
#define SMEM_TOTAL (2 * STG_BYTES)   // 131072

// ---------------------------------------------------------------------------
// Device scratch (no allocation allowed anywhere)
// ---------------------------------------------------------------------------
__device__ __align__(16) float          g_hpart[Hn * Bn];            // [d][b]
__device__ __align__(16) float          g_partial[NBLK * Bn * Sn];   // [j][b][s]
__device__ __align__(16) __nv_bfloat16  g_Whi[Hn * Hn];              // [n][k]
__device__ __align__(16) __nv_bfloat16  g_Wlo[Hn * Hn];              // [n][k]
__device__ __align__(16) __nv_bfloat16  g_Ahi[(size_t)Mrows * Hn];   // [m][k] 64MB
__device__ __align__(16) __nv_bfloat16  g_Alo[(size_t)Mrows * Hn];   // [m][k] 64MB

// ---------------------------------------------------------------------------
// PTX helpers (all baseline compute_100-safe: sm_80-era instructions)
// ---------------------------------------------------------------------------
__device__ __forceinline__ uint32_t smem_u32(const void* p) {
    uint32_t a;
    asm("{ .reg .u64 t; cvta.to.shared.u64 t, %1; cvt.u32.u64 %0, t; }"
        : "=r"(a) : "l"(p));
    return a;
}

#define CP16(daddr, sptr) \
    asm volatile("cp.async.cg.shared.global [%0], [%1], 16;" \
        :: "r"((uint32_t)(daddr)), "l"(__cvta_generic_to_global(sptr)))
#define CP_COMMIT() asm volatile("cp.async.commit_group;" ::: "memory")
#define CP_WAIT1()  asm volatile("cp.async.wait_group 1;" ::: "memory")
#define CP_WAIT0()  asm volatile("cp.async.wait_group 0;" ::: "memory")

#define LDSM4(r, addr) \
    asm volatile("ldmatrix.sync.aligned.m8n8.x4.shared.b16 {%0,%1,%2,%3}, [%4];" \
        : "=r"((r)[0]), "=r"((r)[1]), "=r"((r)[2]), "=r"((r)[3]) \
        : "r"((uint32_t)(addr)))

#define MMA_BF16(d, a, b) \
    asm volatile( \
        "mma.sync.aligned.m16n8k16.row.col.f32.bf16.bf16.f32 " \
        "{%0,%1,%2,%3}, {%4,%5,%6,%7}, {%8,%9}, {%0,%1,%2,%3};" \
        : "+f"((d)[0]), "+f"((d)[1]), "+f"((d)[2]), "+f"((d)[3]) \
        : "r"((a)[0]), "r"((a)[1]), "r"((a)[2]), "r"((a)[3]), \
          "r"((b)[0]), "r"((b)[1]))

// ---------------------------------------------------------------------------
// FMA-only fast tanh (no MUFU)
// ---------------------------------------------------------------------------
__device__ __forceinline__ float fast_tanh(float x) {
    const float C = 7.90531110763549805f;
    float xc = fmaxf(-C, fminf(C, x));
    float x2 = xc * xc;
    float p = -2.76076847742355e-16f;
    p = fmaf(p, x2, 2.00018790482477e-13f);
    p = fmaf(p, x2, -8.60467152213735e-11f);
    p = fmaf(p, x2, 5.12229709037114e-08f);
    p = fmaf(p, x2, 1.48572235717979e-05f);
    p = fmaf(p, x2, 6.37261928875436e-04f);
    p = fmaf(p, x2, 4.89352455891786e-03f);
    p = p * xc;
    float q = 1.19825839466702e-06f;
    q = fmaf(q, x2, 1.18534705686654e-04f);
    q = fmaf(q, x2, 2.26843463243900e-03f);
    q = fmaf(q, x2, 4.89352518554385e-03f);
    float y = __uint_as_float(0x7EF311C3u - __float_as_uint(q));
    y = y * fmaf(-q, y, 2.0f);
    y = y * fmaf(-q, y, 2.0f);
    y = y * fmaf(-q, y, 2.0f);
    return p * y;
}

__device__ __forceinline__ uint32_t pack2(__nv_bfloat16 a, __nv_bfloat16 b) {
    return ((uint32_t)__bfloat16_as_ushort(b) << 16) | __bfloat16_as_ushort(a);
}

// ---------------------------------------------------------------------------
// Kernel 0a: W_e -> transposed bf16 hi/lo  [n][k]
// ---------------------------------------------------------------------------
__global__ __launch_bounds__(256) void wconv_kernel(const float* __restrict__ W_attn)
{
    int idx = blockIdx.x * 256 + threadIdx.x;   // 0..262143
    int k = idx & (Hn - 1);
    int n = idx >> 9;
    float w = W_attn[(size_t)(DHn + k) * Hn + n];
    __nv_bfloat16 hi = __float2bfloat16(w);
    __nv_bfloat16 lo = __float2bfloat16(w - __bfloat162float(hi));
    g_Whi[n * Hn + k] = hi;
    g_Wlo[n * Hn + k] = lo;
}

// ---------------------------------------------------------------------------
// Kernel 0b: enc -> bf16 hi/lo [m][k] (one float4 per thread)
// ---------------------------------------------------------------------------
__global__ __launch_bounds__(256) void aconv_kernel(const float* __restrict__ enc)
{
    size_t i = (size_t)blockIdx.x * 256 + threadIdx.x;   // float4 index
    float4 a = ((const float4*)enc)[i];
    __nv_bfloat16 h0 = __float2bfloat16(a.x);
    __nv_bfloat16 h1 = __float2bfloat16(a.y);
    __nv_bfloat16 h2 = __float2bfloat16(a.z);
    __nv_bfloat16 h3 = __float2bfloat16(a.w);
    __nv_bfloat16 l0 = __float2bfloat16(a.x - __bfloat162float(h0));
    __nv_bfloat16 l1 = __float2bfloat16(a.y - __bfloat162float(h1));
    __nv_bfloat16 l2 = __float2bfloat16(a.z - __bfloat162float(h2));
    __nv_bfloat16 l3 = __float2bfloat16(a.w - __bfloat162float(h3));
    ((uint2*)g_Ahi)[i] = make_uint2(pack2(h0, h1), pack2(h2, h3));
    ((uint2*)g_Alo)[i] = make_uint2(pack2(l0, l1), pack2(l2, l3));
}

// ---------------------------------------------------------------------------
// Kernel 1: hpart[d][b] = hidden[b] @ W_h[:,d] + b_attn[d]   (transposed out)
// ---------------------------------------------------------------------------
__global__ __launch_bounds__(512) void hpart_kernel(
    const float* __restrict__ hidden,
    const float* __restrict__ W_attn,
    const float* __restrict__ b_attn)
{
    __shared__ float red[3 * 128];
    int tid = threadIdx.x;
    int dl = tid & 127;
    int kh = tid >> 7;                   // 0..3
    int b = blockIdx.x;
    int d = blockIdx.y * 128 + dl;

    const float* __restrict__ hrow = hidden + b * DHn + kh * 512;
    const float* __restrict__ Wp = W_attn + (size_t)(kh * 512) * Hn + d;
    float acc = 0.0f;
#pragma unroll 8
    for (int k = 0; k < 512; k++) {
        acc = fmaf(hrow[k], Wp[(size_t)k * Hn], acc);
    }
    if (kh > 0) red[(kh - 1) * 128 + dl] = acc;
    __syncthreads();
    if (kh == 0) {
        acc += red[dl] + red[128 + dl] + red[256 + dl] + b_attn[d];
        g_hpart[(size_t)d * Bn + b] = acc;
    }
}

// ---------------------------------------------------------------------------
// Kernel 2: bf16-split mma.sync GEMM + tanh + v-dot
// grid (512, 4), 256 threads (8 warps: 2M x 4N), tile 128x128, KC=64, 2-stage
// ---------------------------------------------------------------------------
__global__ __launch_bounds__(256) void main_kernel(const float* __restrict__ v)
{
    extern __shared__ char smem[];
    const uint32_t sb = smem_u32(smem);
    const int tid = threadIdx.x;
    const int wid = tid >> 5;
    const int lane = tid & 31;
    const int warp_m = wid >> 2;          // 0..1
    const int warp_n = wid & 3;           // 0..3
    const int rowbase = blockIdx.x * TM;
    const int colbase = blockIdx.y * TN;

    float acc[4][4][4];
#pragma unroll
    for (int mt = 0; mt < 4; mt++)
#pragma unroll
        for (int nt = 0; nt < 4; nt++)
#pragma unroll
            for (int q = 0; q < 4; q++) acc[mt][nt][q] = 0.0f;

    // ---- cp.async loader for one K-chunk into stage s
    auto load_chunk = [&](int c, int s) {
        const int kb = c * KC;
        const uint32_t stg = sb + s * STG_BYTES;
#pragma unroll
        for (int j = 0; j < 4; j++) {
            int unit = tid + j * 256;           // 0..1023
            int row = unit >> 3;                // 0..127
            int u = unit & 7;                   // 16B unit in row
            uint32_t doff = (uint32_t)(row * 128 + ((u * 16) ^ ((row & 7) << 4)));
            const __nv_bfloat16* ga = g_Ahi + (size_t)(rowbase + row) * Hn + kb + u * 8;
            const __nv_bfloat16* gal = g_Alo + (size_t)(rowbase + row) * Hn + kb + u * 8;
            const __nv_bfloat16* gb = g_Whi + (size_t)(colbase + row) * Hn + kb + u * 8;
            const __nv_bfloat16* gbl = g_Wlo + (size_t)(colbase + row) * Hn + kb + u * 8;
            CP16(stg + OFF_AHI + doff, ga);
            CP16(stg + OFF_ALO + doff, gal);
            CP16(stg + OFF_BHI + doff, gb);
            CP16(stg + OFF_BLO + doff, gbl);
        }
    };

    load_chunk(0, 0);
    CP_COMMIT();

    const int arow_lane = lane & 15;
    const int akhalf = lane >> 4;                      // 0/1 -> k0/k8
    const int bn_lane = ((lane >> 4) & 1) * 8 + (lane & 7);
    const int bkhalf = (lane >> 3) & 1;

    for (int c = 0; c < NCHUNK; c++) {
        if (c + 1 < NCHUNK) {
            load_chunk(c + 1, (c + 1) & 1);
            CP_COMMIT();
            CP_WAIT1();
        } else {
            CP_WAIT0();
        }
        __syncthreads();

        const uint32_t stg = sb + (c & 1) * STG_BYTES;
        const uint32_t sA = stg + OFF_AHI;
        const uint32_t sB = stg + OFF_BHI;

#pragma unroll
        for (int ks = 0; ks < 4; ks++) {
            uint32_t ahi[4][4], alo[4][4], bhi[2][4], blo[2][4];
#pragma unroll
            for (int mt = 0; mt < 4; mt++) {
                int row = warp_m * 64 + mt * 16 + arow_lane;
                uint32_t off = (uint32_t)(row * 128 +
                    (((ks * 32) + akhalf * 16) ^ ((row & 7) << 4)));
                LDSM4(ahi[mt], sA + off);
                LDSM4(alo[mt], sA + 16384 + off);
            }
#pragma unroll
            for (int np = 0; np < 2; np++) {
                int row = warp_n * 32 + np * 16 + bn_lane;
                uint32_t off = (uint32_t)(row * 128 +
                    (((ks * 32) + bkhalf * 16) ^ ((row & 7) << 4)));
                LDSM4(bhi[np], sB + off);
                LDSM4(blo[np], sB + 16384 + off);
            }
#pragma unroll
            for (int mt = 0; mt < 4; mt++) {
#pragma unroll
                for (int nt = 0; nt < 4; nt++) {
                    uint32_t* bh = &bhi[nt >> 1][(nt & 1) * 2];
                    uint32_t* bl = &blo[nt >> 1][(nt & 1) * 2];
                    MMA_BF16(acc[mt][nt], ahi[mt], bh);   // hi*hi
                    MMA_BF16(acc[mt][nt], ahi[mt], bl);   // hi*lo
                    MMA_BF16(acc[mt][nt], alo[mt], bh);   // lo*hi
                }
            }
        }
        __syncthreads();
    }

    // ---- Epilogue: reuse smem: hp[col][b] (16KB), v (512B), red (8.7KB)
    float* hp_s = (float*)smem;                        // 128*32
    float* v_s  = (float*)(smem + 16384);              // 128
    float* red  = (float*)(smem + 17408);              // 128*17

    for (int i = tid; i < TN * Bn; i += 256)
        hp_s[i] = g_hpart[(size_t)colbase * Bn + i];   // identical layout: coalesced
    if (tid < TN) v_s[tid] = v[colbase + tid];
    __syncthreads();

    const int tg = lane & 3;
    const int gid = lane >> 2;
#pragma unroll
    for (int mt = 0; mt < 4; mt++) {
        int r0 = warp_m * 64 + mt * 16 + gid;
        int r1 = r0 + 8;
        int b0 = r0 & 31;
        int b1 = r1 & 31;
        float s0 = 0.0f, s1 = 0.0f;
#pragma unroll
        for (int nt = 0; nt < 4; nt++) {
            int c0 = warp_n * 32 + nt * 8 + tg * 2;
            float v0 = v_s[c0], v1 = v_s[c0 + 1];
            float x00 = acc[mt][nt][0] + hp_s[c0 * 32 + b0];
            float x10 = acc[mt][nt][1] + hp_s[(c0 + 1) * 32 + b0];
            float x01 = acc[mt][nt][2] + hp_s[c0 * 32 + b1];
            float x11 = acc[mt][nt][3] + hp_s[(c0 + 1) * 32 + b1];
            s0 = fmaf(fast_tanh(x00), v0, s0);
            s0 = fmaf(fast_tanh(x10), v1, s0);
            s1 = fmaf(fast_tanh(x01), v0, s1);
            s1 = fmaf(fast_tanh(x11), v1, s1);
        }
        red[r0 * 17 + warp_n * 4 + tg] = s0;
        red[r1 * 17 + warp_n * 4 + tg] = s1;
    }
    __syncthreads();

    if (tid < TM) {
        float s = 0.0f;
#pragma unroll
        for (int j = 0; j < 16; j++) s += red[tid * 17 + j];
        int b = tid & 31;
        int seq = blockIdx.x * 4 + (tid >> 5);
        g_partial[blockIdx.y * (Bn * Sn) + b * Sn + seq] = s;
    }
}

// ---------------------------------------------------------------------------
// Kernel 3: sum 4 partials + softmax over s
// ---------------------------------------------------------------------------
__global__ __launch_bounds__(256) void softmax_kernel(float* __restrict__ out)
{
    const int b = blockIdx.x;
    const int tid = threadIdx.x;
    __shared__ float logits[Sn];
    __shared__ float redbuf[256];

    for (int s = tid; s < Sn; s += 256) {
        float t = 0.0f;
#pragma unroll
        for (int j = 0; j < NBLK; j++) t += g_partial[j * (Bn * Sn) + b * Sn + s];
        logits[s] = t;
    }
    __syncthreads();

    float m = -INFINITY;
    for (int s = tid; s < Sn; s += 256) m = fmaxf(m, logits[s]);
    redbuf[tid] = m;
    __syncthreads();
    for (int off = 128; off > 0; off >>= 1) {
        if (tid < off) redbuf[tid] = fmaxf(redbuf[tid], redbuf[tid + off]);
        __syncthreads();
    }
    m = redbuf[0];
    __syncthreads();

    float sum = 0.0f;
    for (int s = tid; s < Sn; s += 256) {
        float e = expf(logits[s] - m);
        logits[s] = e;
        sum += e;
    }
    redbuf[tid] = sum;
    __syncthreads();
    for (int off = 128; off > 0; off >>= 1) {
        if (tid < off) redbuf[tid] += redbuf[tid + off];
        __syncthreads();
    }
    const float inv = 1.0f / redbuf[0];
    __syncthreads();

    for (int s = tid; s < Sn; s += 256) {
        out[b * Sn + s] = logits[s] * inv;
    }
}

// ---------------------------------------------------------------------------
// Launch
// ---------------------------------------------------------------------------
extern "C" void kernel_launch(void* const* d_in, const int* in_sizes, int n_in,
                              void* d_out, int out_size)
{
    const float* hidden = (const float*)d_in[0];
    const float* enc    = (const float*)d_in[1];
    const float* W_attn = (const float*)d_in[2];
    const float* b_attn = (const float*)d_in[3];
    const float* v      = (const float*)d_in[4];
    float* out = (float*)d_out;

    cudaFuncSetAttribute(main_kernel,
                         cudaFuncAttributeMaxDynamicSharedMemorySize, SMEM_TOTAL);

    wconv_kernel<<<1024, 256>>>(W_attn);
    aconv_kernel<<<(Mrows * Hn / 4) / 256, 256>>>(enc);
    hpart_kernel<<<dim3(Bn, 4), 512>>>(hidden, W_attn, b_attn);
    main_kernel<<<dim3(Mrows / TM, NBLK), 256, SMEM_TOTAL>>>(v);
    softmax_kernel<<<Bn, 256>>>(out);
}

// round 4
// speedup vs baseline: 3.1290x; 1.2009x over previous
#include <cuda_runtime.h>
#include <cuda_bf16.h>
#include <math.h>
#include <stdint.h>

// ---------------------------------------------------------------------------
// Problem constants
// ---------------------------------------------------------------------------
#define Hn   512
#define DHn  2048
#define Bn   32
#define Sn   2048
#define Mrows (Sn * Bn)       // 65536

// GEMM tiling
#define TM 128
#define TN 128
#define KC 64
#define NCHUNK (Hn / KC)      // 8
#define NBLK (Hn / TN)        // 4

// smem: A tile 128x64 f32 (32KB) + B tile 128x64 f32 (32KB) per stage, 2 stages
#define STG_BYTES 65536
#define OFF_A 0
#define OFF_B 32768
#define SMEM_TOTAL (2 * STG_BYTES)   // 131072

// ---------------------------------------------------------------------------
// Device scratch
// ---------------------------------------------------------------------------
__device__ __align__(16) float g_hpart[Hn * Bn];            // [d][b]
__device__ __align__(16) float g_partial[NBLK * Bn * Sn];   // [j][b][s]
__device__ __align__(16) float g_Wt[Hn * Hn];               // [n][k], tf32-rounded

// ---------------------------------------------------------------------------
// PTX helpers (compute_100-safe, sm_80-era)
// ---------------------------------------------------------------------------
__device__ __forceinline__ uint32_t smem_u32(const void* p) {
    uint32_t a;
    asm("{ .reg .u64 t; cvta.to.shared.u64 t, %1; cvt.u32.u64 %0, t; }"
        : "=r"(a) : "l"(p));
    return a;
}

#define CP16(daddr, sptr) \
    asm volatile("cp.async.cg.shared.global [%0], [%1], 16;" \
        :: "r"((uint32_t)(daddr)), "l"(__cvta_generic_to_global(sptr)))
#define CP_COMMIT() asm volatile("cp.async.commit_group;" ::: "memory")
#define CP_WAIT1()  asm volatile("cp.async.wait_group 1;" ::: "memory")
#define CP_WAIT0()  asm volatile("cp.async.wait_group 0;" ::: "memory")

#define LDSM4(r, addr) \
    asm volatile("ldmatrix.sync.aligned.m8n8.x4.shared.b16 {%0,%1,%2,%3}, [%4];" \
        : "=r"((r)[0]), "=r"((r)[1]), "=r"((r)[2]), "=r"((r)[3]) \
        : "r"((uint32_t)(addr)))

#define MMA_TF32(d, a, b0, b1) \
    asm volatile( \
        "mma.sync.aligned.m16n8k8.row.col.f32.tf32.tf32.f32 " \
        "{%0,%1,%2,%3}, {%4,%5,%6,%7}, {%8,%9}, {%0,%1,%2,%3};" \
        : "+f"((d)[0]), "+f"((d)[1]), "+f"((d)[2]), "+f"((d)[3]) \
        : "r"((a)[0]), "r"((a)[1]), "r"((a)[2]), "r"((a)[3]), \
          "r"(b0), "r"(b1))

#define CVT_TF32(dst, src) \
    asm volatile("cvt.rna.tf32.f32 %0, %1;" : "=r"(dst) : "r"(src))

// ---------------------------------------------------------------------------
// FMA-only fast tanh (no MUFU)
// ---------------------------------------------------------------------------
__device__ __forceinline__ float fast_tanh(float x) {
    const float C = 7.90531110763549805f;
    float xc = fmaxf(-C, fminf(C, x));
    float x2 = xc * xc;
    float p = -2.76076847742355e-16f;
    p = fmaf(p, x2, 2.00018790482477e-13f);
    p = fmaf(p, x2, -8.60467152213735e-11f);
    p = fmaf(p, x2, 5.12229709037114e-08f);
    p = fmaf(p, x2, 1.48572235717979e-05f);
    p = fmaf(p, x2, 6.37261928875436e-04f);
    p = fmaf(p, x2, 4.89352455891786e-03f);
    p = p * xc;
    float q = 1.19825839466702e-06f;
    q = fmaf(q, x2, 1.18534705686654e-04f);
    q = fmaf(q, x2, 2.26843463243900e-03f);
    q = fmaf(q, x2, 4.89352518554385e-03f);
    float y = __uint_as_float(0x7EF311C3u - __float_as_uint(q));
    y = y * fmaf(-q, y, 2.0f);
    y = y * fmaf(-q, y, 2.0f);
    y = y * fmaf(-q, y, 2.0f);
    return p * y;
}

// ---------------------------------------------------------------------------
// Kernel 0: W_e -> transposed, tf32-rounded fp32  g_Wt[n][k]
// ---------------------------------------------------------------------------
__global__ __launch_bounds__(256) void wconv_kernel(const float* __restrict__ W_attn)
{
    int idx = blockIdx.x * 256 + threadIdx.x;   // 0..262143
    int n = idx & (Hn - 1);                     // coalesced read along n
    int k = idx >> 9;
    uint32_t w = __float_as_uint(W_attn[(size_t)(DHn + k) * Hn + n]);
    uint32_t r;
    CVT_TF32(r, w);
    g_Wt[(size_t)n * Hn + k] = __uint_as_float(r);
}

// ---------------------------------------------------------------------------
// Kernel 1: hpart[d][b] = hidden[b] @ W_h[:,d] + b_attn[d]   (transposed out)
// ---------------------------------------------------------------------------
__global__ __launch_bounds__(512) void hpart_kernel(
    const float* __restrict__ hidden,
    const float* __restrict__ W_attn,
    const float* __restrict__ b_attn)
{
    __shared__ float red[3 * 128];
    int tid = threadIdx.x;
    int dl = tid & 127;
    int kh = tid >> 7;                   // 0..3
    int b = blockIdx.x;
    int d = blockIdx.y * 128 + dl;

    const float* __restrict__ hrow = hidden + b * DHn + kh * 512;
    const float* __restrict__ Wp = W_attn + (size_t)(kh * 512) * Hn + d;
    float acc = 0.0f;
#pragma unroll 8
    for (int k = 0; k < 512; k++) {
        acc = fmaf(hrow[k], Wp[(size_t)k * Hn], acc);
    }
    if (kh > 0) red[(kh - 1) * 128 + dl] = acc;
    __syncthreads();
    if (kh == 0) {
        acc += red[dl] + red[128 + dl] + red[256 + dl] + b_attn[d];
        g_hpart[(size_t)d * Bn + b] = acc;
    }
}

// ---------------------------------------------------------------------------
// Kernel 2: single-pass tf32 mma GEMM + tanh + v-dot
// grid (512, 4), 256 threads (8 warps: 2M x 4N), tile 128x128, KC=64, 2-stage
// ---------------------------------------------------------------------------
__global__ __launch_bounds__(256) void main_kernel(
    const float* __restrict__ enc,    // (65536, 512) fp32
    const float* __restrict__ v)
{
    extern __shared__ char smem[];
    const uint32_t sb = smem_u32(smem);
    const int tid = threadIdx.x;
    const int wid = tid >> 5;
    const int lane = tid & 31;
    const int warp_m = wid >> 2;          // 0..1
    const int warp_n = wid & 3;           // 0..3
    const int rowbase = blockIdx.x * TM;
    const int colbase = blockIdx.y * TN;

    float acc[4][4][4];
#pragma unroll
    for (int mt = 0; mt < 4; mt++)
#pragma unroll
        for (int nt = 0; nt < 4; nt++)
#pragma unroll
            for (int q = 0; q < 4; q++) acc[mt][nt][q] = 0.0f;

    // cp.async one K-chunk (A 128x64 f32 + B 128x64 f32) into stage s.
    // Row = 256B (16 x 16B units); swizzle: phys_unit = u ^ (row & 7)
    auto load_chunk = [&](int c, int s) {
        const int kb = c * KC;
        const uint32_t stg = sb + s * STG_BYTES;
#pragma unroll
        for (int j = 0; j < 8; j++) {
            int unit = tid + j * 256;           // 0..2047
            int row = unit >> 4;                // 0..127
            int u = unit & 15;
            uint32_t doff = (uint32_t)(row * 256 + 16 * (u ^ (row & 7)));
            CP16(stg + OFF_A + doff, enc + (size_t)(rowbase + row) * Hn + kb + u * 4);
            CP16(stg + OFF_B + doff, g_Wt + (size_t)(colbase + row) * Hn + kb + u * 4);
        }
    };

    load_chunk(0, 0);
    CP_COMMIT();

    // ldmatrix per-lane addressing (32-bit elements, row-major 256B rows)
    // A frag (one m16 tile, one k8 step): matrices over {rowhalf, khalf}
    const int a_r   = ((lane >> 3) & 1) * 8 + (lane & 7);  // row within 16
    const int a_uo  = (lane >> 4);                         // unit offset 0/1
    // B frag x4 (two n-octets, one k8 step)
    const int b_r   = ((lane >> 4) & 1) * 8 + (lane & 7);  // n within 16
    const int b_uo  = ((lane >> 3) & 1);                   // unit offset 0/1

    uint32_t afr[2][4][4];
    uint32_t bfr[2][2][4];

    for (int c = 0; c < NCHUNK; c++) {
        if (c + 1 < NCHUNK) {
            load_chunk(c + 1, (c + 1) & 1);
            CP_COMMIT();
            CP_WAIT1();
        } else {
            CP_WAIT0();
        }
        __syncthreads();

        const uint32_t stg = sb + (c & 1) * STG_BYTES;
        const uint32_t sA = stg + OFF_A;
        const uint32_t sB = stg + OFF_B;

        auto ld_frags = [&](int ks, int buf) {
            const int ub = ks * 2;
#pragma unroll
            for (int mt = 0; mt < 4; mt++) {
                int row = warp_m * 64 + mt * 16 + a_r;
                uint32_t off = (uint32_t)(row * 256 + 16 * ((ub + a_uo) ^ (row & 7)));
                LDSM4(afr[buf][mt], sA + off);
            }
#pragma unroll
            for (int pr = 0; pr < 2; pr++) {
                int n = warp_n * 32 + pr * 16 + b_r;
                uint32_t off = (uint32_t)(n * 256 + 16 * ((ub + b_uo) ^ (n & 7)));
                LDSM4(bfr[buf][pr], sB + off);
            }
        };

        auto compute = [&](int buf) {
            uint32_t ca[4][4];
#pragma unroll
            for (int mt = 0; mt < 4; mt++)
#pragma unroll
                for (int q = 0; q < 4; q++)
                    CVT_TF32(ca[mt][q], afr[buf][mt][q]);
#pragma unroll
            for (int mt = 0; mt < 4; mt++) {
#pragma unroll
                for (int pr = 0; pr < 2; pr++) {
                    // bfr[pr]: r0,r1 = octet0 (b0,b1); r2,r3 = octet1
                    MMA_TF32(acc[mt][pr * 2 + 0], ca[mt], bfr[buf][pr][0], bfr[buf][pr][1]);
                    MMA_TF32(acc[mt][pr * 2 + 1], ca[mt], bfr[buf][pr][2], bfr[buf][pr][3]);
                }
            }
        };

        ld_frags(0, 0);
#pragma unroll
        for (int ks = 0; ks < 8; ks++) {
            if (ks < 7) ld_frags(ks + 1, (ks + 1) & 1);
            compute(ks & 1);
        }
        __syncthreads();
    }

    // ---- Epilogue: hp[col][b] (16KB), v (512B), red (8.7KB) in smem
    float* hp_s = (float*)smem;                        // 128*32
    float* v_s  = (float*)(smem + 16384);              // 128
    float* red  = (float*)(smem + 17408);              // 128*17

    for (int i = tid; i < TN * Bn; i += 256)
        hp_s[i] = g_hpart[(size_t)colbase * Bn + i];
    if (tid < TN) v_s[tid] = v[colbase + tid];
    __syncthreads();

    const int tg = lane & 3;
    const int gid = lane >> 2;
#pragma unroll
    for (int mt = 0; mt < 4; mt++) {
        int r0 = warp_m * 64 + mt * 16 + gid;
        int r1 = r0 + 8;
        int b0 = r0 & 31;
        int b1 = r1 & 31;
        float s0 = 0.0f, s1 = 0.0f;
#pragma unroll
        for (int nt = 0; nt < 4; nt++) {
            int c0 = warp_n * 32 + nt * 8 + tg * 2;
            float v0 = v_s[c0], v1 = v_s[c0 + 1];
            float x00 = acc[mt][nt][0] + hp_s[c0 * 32 + b0];
            float x10 = acc[mt][nt][1] + hp_s[(c0 + 1) * 32 + b0];
            float x01 = acc[mt][nt][2] + hp_s[c0 * 32 + b1];
            float x11 = acc[mt][nt][3] + hp_s[(c0 + 1) * 32 + b1];
            s0 = fmaf(fast_tanh(x00), v0, s0);
            s0 = fmaf(fast_tanh(x10), v1, s0);
            s1 = fmaf(fast_tanh(x01), v0, s1);
            s1 = fmaf(fast_tanh(x11), v1, s1);
        }
        red[r0 * 17 + warp_n * 4 + tg] = s0;
        red[r1 * 17 + warp_n * 4 + tg] = s1;
    }
    __syncthreads();

    if (tid < TM) {
        float s = 0.0f;
#pragma unroll
        for (int j = 0; j < 16; j++) s += red[tid * 17 + j];
        int b = tid & 31;
        int seq = blockIdx.x * 4 + (tid >> 5);
        g_partial[blockIdx.y * (Bn * Sn) + b * Sn + seq] = s;
    }
}

// ---------------------------------------------------------------------------
// Kernel 3: sum 4 partials + softmax over s
// ---------------------------------------------------------------------------
__global__ __launch_bounds__(256) void softmax_kernel(float* __restrict__ out)
{
    const int b = blockIdx.x;
    const int tid = threadIdx.x;
    __shared__ float logits[Sn];
    __shared__ float redbuf[256];

    for (int s = tid; s < Sn; s += 256) {
        float t = 0.0f;
#pragma unroll
        for (int j = 0; j < NBLK; j++) t += g_partial[j * (Bn * Sn) + b * Sn + s];
        logits[s] = t;
    }
    __syncthreads();

    float m = -INFINITY;
    for (int s = tid; s < Sn; s += 256) m = fmaxf(m, logits[s]);
    redbuf[tid] = m;
    __syncthreads();
    for (int off = 128; off > 0; off >>= 1) {
        if (tid < off) redbuf[tid] = fmaxf(redbuf[tid], redbuf[tid + off]);
        __syncthreads();
    }
    m = redbuf[0];
    __syncthreads();

    float sum = 0.0f;
    for (int s = tid; s < Sn; s += 256) {
        float e = expf(logits[s] - m);
        logits[s] = e;
        sum += e;
    }
    redbuf[tid] = sum;
    __syncthreads();
    for (int off = 128; off > 0; off >>= 1) {
        if (tid < off) redbuf[tid] += redbuf[tid + off];
        __syncthreads();
    }
    const float inv = 1.0f / redbuf[0];
    __syncthreads();

    for (int s = tid; s < Sn; s += 256) {
        out[b * Sn + s] = logits[s] * inv;
    }
}

// ---------------------------------------------------------------------------
// Launch
// ---------------------------------------------------------------------------
extern "C" void kernel_launch(void* const* d_in, const int* in_sizes, int n_in,
                              void* d_out, int out_size)
{
    const float* hidden = (const float*)d_in[0];
    const float* enc    = (const float*)d_in[1];
    const float* W_attn = (const float*)d_in[2];
    const float* b_attn = (const float*)d_in[3];
    const float* v      = (const float*)d_in[4];
    float* out = (float*)d_out;

    cudaFuncSetAttribute(main_kernel,
                         cudaFuncAttributeMaxDynamicSharedMemorySize, SMEM_TOTAL);

    wconv_kernel<<<1024, 256>>>(W_attn);
    hpart_kernel<<<dim3(Bn, 4), 512>>>(hidden, W_attn, b_attn);
    main_kernel<<<dim3(Mrows / TM, NBLK), 256, SMEM_TOTAL>>>(enc, v);
    softmax_kernel<<<Bn, 256>>>(out);
}

// round 5
// speedup vs baseline: 3.7195x; 1.1887x over previous
#include <cuda_runtime.h>
#include <cuda_bf16.h>
#include <math.h>
#include <stdint.h>

// ---------------------------------------------------------------------------
// Problem constants
// ---------------------------------------------------------------------------
#define Hn   512
#define DHn  2048
#define Bn   32
#define Sn   2048
#define Mrows (Sn * Bn)       // 65536

// GEMM tiling
#define TM 256
#define TN 128
#define KC 64
#define NCHUNK (Hn / KC)      // 8
#define NBLK (Hn / TN)        // 4
#define NTHREADS 512

// smem: A tile 256x64 f32 (64KB) + B tile 128x64 f32 (32KB) per stage, 2 stages
#define OFF_A 0
#define OFF_B 65536
#define STG_BYTES 98304
#define SMEM_TOTAL (2 * STG_BYTES)   // 196608

// ---------------------------------------------------------------------------
// Device scratch
// ---------------------------------------------------------------------------
__device__ __align__(16) float g_hpart[Hn * Bn];            // [d][b]
__device__ __align__(16) float g_partial[NBLK * Bn * Sn];   // [j][b][s]
__device__ __align__(16) float g_Wt[Hn * Hn];               // [n][k], tf32-rounded

// ---------------------------------------------------------------------------
// PTX helpers (compute_100-safe, sm_80-era)
// ---------------------------------------------------------------------------
__device__ __forceinline__ uint32_t smem_u32(const void* p) {
    uint32_t a;
    asm("{ .reg .u64 t; cvta.to.shared.u64 t, %1; cvt.u32.u64 %0, t; }"
        : "=r"(a) : "l"(p));
    return a;
}

#define CP16(daddr, sptr) \
    asm volatile("cp.async.cg.shared.global [%0], [%1], 16;" \
        :: "r"((uint32_t)(daddr)), "l"(__cvta_generic_to_global(sptr)))
#define CP_COMMIT() asm volatile("cp.async.commit_group;" ::: "memory")
#define CP_WAIT1()  asm volatile("cp.async.wait_group 1;" ::: "memory")
#define CP_WAIT0()  asm volatile("cp.async.wait_group 0;" ::: "memory")

#define LDSM4(r, addr) \
    asm volatile("ldmatrix.sync.aligned.m8n8.x4.shared.b16 {%0,%1,%2,%3}, [%4];" \
        : "=r"((r)[0]), "=r"((r)[1]), "=r"((r)[2]), "=r"((r)[3]) \
        : "r"((uint32_t)(addr)))

#define MMA_TF32(d, a, b0, b1) \
    asm volatile( \
        "mma.sync.aligned.m16n8k8.row.col.f32.tf32.tf32.f32 " \
        "{%0,%1,%2,%3}, {%4,%5,%6,%7}, {%8,%9}, {%0,%1,%2,%3};" \
        : "+f"((d)[0]), "+f"((d)[1]), "+f"((d)[2]), "+f"((d)[3]) \
        : "r"((a)[0]), "r"((a)[1]), "r"((a)[2]), "r"((a)[3]), \
          "r"(b0), "r"(b1))

#define CVT_TF32_IP(x) \
    asm volatile("cvt.rna.tf32.f32 %0, %0;" : "+r"(x))

#define CVT_TF32(dst, src) \
    asm volatile("cvt.rna.tf32.f32 %0, %1;" : "=r"(dst) : "r"(src))

// ---------------------------------------------------------------------------
// FMA-only fast tanh (no MUFU)
// ---------------------------------------------------------------------------
__device__ __forceinline__ float fast_tanh(float x) {
    const float C = 7.90531110763549805f;
    float xc = fmaxf(-C, fminf(C, x));
    float x2 = xc * xc;
    float p = -2.76076847742355e-16f;
    p = fmaf(p, x2, 2.00018790482477e-13f);
    p = fmaf(p, x2, -8.60467152213735e-11f);
    p = fmaf(p, x2, 5.12229709037114e-08f);
    p = fmaf(p, x2, 1.48572235717979e-05f);
    p = fmaf(p, x2, 6.37261928875436e-04f);
    p = fmaf(p, x2, 4.89352455891786e-03f);
    p = p * xc;
    float q = 1.19825839466702e-06f;
    q = fmaf(q, x2, 1.18534705686654e-04f);
    q = fmaf(q, x2, 2.26843463243900e-03f);
    q = fmaf(q, x2, 4.89352518554385e-03f);
    float y = __uint_as_float(0x7EF311C3u - __float_as_uint(q));
    y = y * fmaf(-q, y, 2.0f);
    y = y * fmaf(-q, y, 2.0f);
    y = y * fmaf(-q, y, 2.0f);
    return p * y;
}

// ---------------------------------------------------------------------------
// Kernel 0: W_e -> transposed, tf32-rounded fp32  g_Wt[n][k]
// ---------------------------------------------------------------------------
__global__ __launch_bounds__(256) void wconv_kernel(const float* __restrict__ W_attn)
{
    int idx = blockIdx.x * 256 + threadIdx.x;   // 0..262143
    int n = idx & (Hn - 1);                     // coalesced read along n
    int k = idx >> 9;
    uint32_t w = __float_as_uint(W_attn[(size_t)(DHn + k) * Hn + n]);
    uint32_t r;
    CVT_TF32(r, w);
    g_Wt[(size_t)n * Hn + k] = __uint_as_float(r);
}

// ---------------------------------------------------------------------------
// Kernel 1: hpart[d][b] = hidden[b] @ W_h[:,d] + b_attn[d]   (transposed out)
// ---------------------------------------------------------------------------
__global__ __launch_bounds__(512) void hpart_kernel(
    const float* __restrict__ hidden,
    const float* __restrict__ W_attn,
    const float* __restrict__ b_attn)
{
    __shared__ float red[3 * 128];
    int tid = threadIdx.x;
    int dl = tid & 127;
    int kh = tid >> 7;                   // 0..3
    int b = blockIdx.x;
    int d = blockIdx.y * 128 + dl;

    const float* __restrict__ hrow = hidden + b * DHn + kh * 512;
    const float* __restrict__ Wp = W_attn + (size_t)(kh * 512) * Hn + d;
    float acc = 0.0f;
#pragma unroll 8
    for (int k = 0; k < 512; k++) {
        acc = fmaf(hrow[k], Wp[(size_t)k * Hn], acc);
    }
    if (kh > 0) red[(kh - 1) * 128 + dl] = acc;
    __syncthreads();
    if (kh == 0) {
        acc += red[dl] + red[128 + dl] + red[256 + dl] + b_attn[d];
        g_hpart[(size_t)d * Bn + b] = acc;
    }
}

// ---------------------------------------------------------------------------
// Kernel 2: single-pass tf32 mma GEMM + tanh + v-dot
// grid (NBLK, Mrows/TM) = (4, 256); 512 threads (16 warps: 4M x 4N)
// tile 256x128, KC=64, 2-stage cp.async
// ---------------------------------------------------------------------------
__global__ __launch_bounds__(NTHREADS, 1) void main_kernel(
    const float* __restrict__ enc,    // (65536, 512) fp32
    const float* __restrict__ v)
{
    extern __shared__ char smem[];
    const uint32_t sb = smem_u32(smem);
    const int tid = threadIdx.x;
    const int wid = tid >> 5;
    const int lane = tid & 31;
    const int warp_m = wid >> 2;          // 0..3
    const int warp_n = wid & 3;           // 0..3
    const int colbase = blockIdx.x * TN;
    const int rowbase = blockIdx.y * TM;

    float acc[4][4][4];
#pragma unroll
    for (int mt = 0; mt < 4; mt++)
#pragma unroll
        for (int nt = 0; nt < 4; nt++)
#pragma unroll
            for (int q = 0; q < 4; q++) acc[mt][nt][q] = 0.0f;

    // cp.async one K-chunk (A 256x64 f32 + B 128x64 f32) into stage s.
    // Row = 256B (16 x 16B units); swizzle: phys_unit = u ^ (row & 7)
    auto load_chunk = [&](int c, int s) {
        const int kb = c * KC;
        const uint32_t stg = sb + s * STG_BYTES;
#pragma unroll
        for (int j = 0; j < 8; j++) {           // A: 4096 units
            int unit = tid + j * NTHREADS;
            int row = unit >> 4;
            int u = unit & 15;
            uint32_t doff = (uint32_t)(row * 256 + 16 * (u ^ (row & 7)));
            CP16(stg + OFF_A + doff, enc + (size_t)(rowbase + row) * Hn + kb + u * 4);
        }
#pragma unroll
        for (int j = 0; j < 4; j++) {           // B: 2048 units
            int unit = tid + j * NTHREADS;
            int row = unit >> 4;
            int u = unit & 15;
            uint32_t doff = (uint32_t)(row * 256 + 16 * (u ^ (row & 7)));
            CP16(stg + OFF_B + doff, g_Wt + (size_t)(colbase + row) * Hn + kb + u * 4);
        }
    };

    load_chunk(0, 0);
    CP_COMMIT();

    // ldmatrix per-lane addressing (32-bit elements in 16-bit ldmatrix clothing)
    const int a_r  = ((lane >> 3) & 1) * 8 + (lane & 7);  // row within m16
    const int a_uo = (lane >> 4);                         // 16B-unit offset 0/1
    const int b_r  = ((lane >> 4) & 1) * 8 + (lane & 7);  // n within 16
    const int b_uo = ((lane >> 3) & 1);

    for (int c = 0; c < NCHUNK; c++) {
        if (c + 1 < NCHUNK) {
            load_chunk(c + 1, (c + 1) & 1);
            CP_COMMIT();
            CP_WAIT1();
        } else {
            CP_WAIT0();
        }
        __syncthreads();

        const uint32_t stg = sb + (c & 1) * STG_BYTES;
        const uint32_t sA = stg + OFF_A;
        const uint32_t sB = stg + OFF_B;

#pragma unroll
        for (int ks = 0; ks < 8; ks++) {
            const int ub = ks * 2;
            uint32_t afr[4][4], bfr[2][4];
#pragma unroll
            for (int mt = 0; mt < 4; mt++) {
                int row = warp_m * 64 + mt * 16 + a_r;
                uint32_t off = (uint32_t)(row * 256 + 16 * ((ub + a_uo) ^ (row & 7)));
                LDSM4(afr[mt], sA + off);
            }
#pragma unroll
            for (int pr = 0; pr < 2; pr++) {
                int n = warp_n * 32 + pr * 16 + b_r;
                uint32_t off = (uint32_t)(n * 256 + 16 * ((ub + b_uo) ^ (n & 7)));
                LDSM4(bfr[pr], sB + off);
            }
#pragma unroll
            for (int mt = 0; mt < 4; mt++)
#pragma unroll
                for (int q = 0; q < 4; q++)
                    CVT_TF32_IP(afr[mt][q]);
#pragma unroll
            for (int mt = 0; mt < 4; mt++) {
#pragma unroll
                for (int pr = 0; pr < 2; pr++) {
                    MMA_TF32(acc[mt][pr * 2 + 0], afr[mt], bfr[pr][0], bfr[pr][1]);
                    MMA_TF32(acc[mt][pr * 2 + 1], afr[mt], bfr[pr][2], bfr[pr][3]);
                }
            }
        }
        __syncthreads();
    }

    // ---- Epilogue: hp[col][b] (16KB), v (512B), red (256x17 = 17.4KB)
    float* hp_s = (float*)smem;                        // 128*32
    float* v_s  = (float*)(smem + 16384);              // 128
    float* red  = (float*)(smem + 17408);              // 256*17

    for (int i = tid; i < TN * Bn; i += NTHREADS)
        hp_s[i] = g_hpart[(size_t)colbase * Bn + i];
    if (tid < TN) v_s[tid] = v[colbase + tid];
    __syncthreads();

    const int tg = lane & 3;
    const int gid = lane >> 2;
#pragma unroll
    for (int mt = 0; mt < 4; mt++) {
        int r0 = warp_m * 64 + mt * 16 + gid;
        int r1 = r0 + 8;
        int b0 = r0 & 31;
        int b1 = r1 & 31;
        float s0 = 0.0f, s1 = 0.0f;
#pragma unroll
        for (int nt = 0; nt < 4; nt++) {
            int c0 = warp_n * 32 + nt * 8 + tg * 2;
            float v0 = v_s[c0], v1 = v_s[c0 + 1];
            float x00 = acc[mt][nt][0] + hp_s[c0 * 32 + b0];
            float x10 = acc[mt][nt][1] + hp_s[(c0 + 1) * 32 + b0];
            float x01 = acc[mt][nt][2] + hp_s[c0 * 32 + b1];
            float x11 = acc[mt][nt][3] + hp_s[(c0 + 1) * 32 + b1];
            s0 = fmaf(fast_tanh(x00), v0, s0);
            s0 = fmaf(fast_tanh(x10), v1, s0);
            s1 = fmaf(fast_tanh(x01), v0, s1);
            s1 = fmaf(fast_tanh(x11), v1, s1);
        }
        red[r0 * 17 + warp_n * 4 + tg] = s0;
        red[r1 * 17 + warp_n * 4 + tg] = s1;
    }
    __syncthreads();

    if (tid < TM) {
        float s = 0.0f;
#pragma unroll
        for (int j = 0; j < 16; j++) s += red[tid * 17 + j];
        int b = tid & 31;
        int seq = blockIdx.y * (TM / Bn) + (tid >> 5);
        g_partial[blockIdx.x * (Bn * Sn) + b * Sn + seq] = s;
    }
}

// ---------------------------------------------------------------------------
// Kernel 3: sum 4 partials + softmax over s
// ---------------------------------------------------------------------------
__global__ __launch_bounds__(256) void softmax_kernel(float* __restrict__ out)
{
    const int b = blockIdx.x;
    const int tid = threadIdx.x;
    __shared__ float logits[Sn];
    __shared__ float redbuf[256];

    for (int s = tid; s < Sn; s += 256) {
        float t = 0.0f;
#pragma unroll
        for (int j = 0; j < NBLK; j++) t += g_partial[j * (Bn * Sn) + b * Sn + s];
        logits[s] = t;
    }
    __syncthreads();

    float m = -INFINITY;
    for (int s = tid; s < Sn; s += 256) m = fmaxf(m, logits[s]);
    redbuf[tid] = m;
    __syncthreads();
    for (int off = 128; off > 0; off >>= 1) {
        if (tid < off) redbuf[tid] = fmaxf(redbuf[tid], redbuf[tid + off]);
        __syncthreads();
    }
    m = redbuf[0];
    __syncthreads();

    float sum = 0.0f;
    for (int s = tid; s < Sn; s += 256) {
        float e = expf(logits[s] - m);
        logits[s] = e;
        sum += e;
    }
    redbuf[tid] = sum;
    __syncthreads();
    for (int off = 128; off > 0; off >>= 1) {
        if (tid < off) redbuf[tid] += redbuf[tid + off];
        __syncthreads();
    }
    const float inv = 1.0f / redbuf[0];
    __syncthreads();

    for (int s = tid; s < Sn; s += 256) {
        out[b * Sn + s] = logits[s] * inv;
    }
}

// ---------------------------------------------------------------------------
// Launch
// ---------------------------------------------------------------------------
extern "C" void kernel_launch(void* const* d_in, const int* in_sizes, int n_in,
                              void* d_out, int out_size)
{
    const float* hidden = (const float*)d_in[0];
    const float* enc    = (const float*)d_in[1];
    const float* W_attn = (const float*)d_in[2];
    const float* b_attn = (const float*)d_in[3];
    const float* v      = (const float*)d_in[4];
    float* out = (float*)d_out;

    cudaFuncSetAttribute(main_kernel,
                         cudaFuncAttributeMaxDynamicSharedMemorySize, SMEM_TOTAL);

    wconv_kernel<<<1024, 256>>>(W_attn);
    hpart_kernel<<<dim3(Bn, 4), 512>>>(hidden, W_attn, b_attn);
    // grid.x = column blocks so consecutive CTAs share the same A row-tile (L2 dedup)
    main_kernel<<<dim3(NBLK, Mrows / TM), NTHREADS, SMEM_TOTAL>>>(enc, v);
    softmax_kernel<<<Bn, 256>>>(out);
}

// round 6
// speedup vs baseline: 3.9173x; 1.0532x over previous
#include <cuda_runtime.h>
#include <cuda_bf16.h>
#include <math.h>
#include <stdint.h>

// ---------------------------------------------------------------------------
// Problem constants
// ---------------------------------------------------------------------------
#define Hn   512
#define DHn  2048
#define Bn   32
#define Sn   2048
#define Mrows (Sn * Bn)       // 65536

// GEMM tiling: 128x128 tile, KC=32, 2 CTAs/SM
#define TM 128
#define TN 128
#define KC 32
#define NCHUNK (Hn / KC)      // 16
#define NBLK (Hn / TN)        // 4
#define NTHREADS 256

// smem: A tile 128x32 f32 (16KB) + B tile 128x32 f32 (16KB) per stage, 2 stages
#define OFF_A 0
#define OFF_B 16384
#define STG_BYTES 32768
#define SMEM_TOTAL (2 * STG_BYTES)   // 65536 -> 2 CTAs/SM

// ---------------------------------------------------------------------------
// Device scratch
// ---------------------------------------------------------------------------
__device__ __align__(16) float g_hpart[Hn * Bn];            // [d][b]
__device__ __align__(16) float g_partial[NBLK * Bn * Sn];   // [j][b][s]
__device__ __align__(16) float g_Wt[Hn * Hn];               // [n][k], tf32-rounded

// ---------------------------------------------------------------------------
// PTX helpers (compute_100-safe, sm_80-era)
// ---------------------------------------------------------------------------
__device__ __forceinline__ uint32_t smem_u32(const void* p) {
    uint32_t a;
    asm("{ .reg .u64 t; cvta.to.shared.u64 t, %1; cvt.u32.u64 %0, t; }"
        : "=r"(a) : "l"(p));
    return a;
}

#define CP16(daddr, sptr) \
    asm volatile("cp.async.cg.shared.global [%0], [%1], 16;" \
        :: "r"((uint32_t)(daddr)), "l"(__cvta_generic_to_global(sptr)))
#define CP_COMMIT() asm volatile("cp.async.commit_group;" ::: "memory")
#define CP_WAIT1()  asm volatile("cp.async.wait_group 1;" ::: "memory")
#define CP_WAIT0()  asm volatile("cp.async.wait_group 0;" ::: "memory")

#define LDSM4(r, addr) \
    asm volatile("ldmatrix.sync.aligned.m8n8.x4.shared.b16 {%0,%1,%2,%3}, [%4];" \
        : "=r"((r)[0]), "=r"((r)[1]), "=r"((r)[2]), "=r"((r)[3]) \
        : "r"((uint32_t)(addr)))

#define MMA_TF32(d, a, b0, b1) \
    asm volatile( \
        "mma.sync.aligned.m16n8k8.row.col.f32.tf32.tf32.f32 " \
        "{%0,%1,%2,%3}, {%4,%5,%6,%7}, {%8,%9}, {%0,%1,%2,%3};" \
        : "+f"((d)[0]), "+f"((d)[1]), "+f"((d)[2]), "+f"((d)[3]) \
        : "r"((a)[0]), "r"((a)[1]), "r"((a)[2]), "r"((a)[3]), \
          "r"(b0), "r"(b1))

#define CVT_TF32_IP(x) \
    asm volatile("cvt.rna.tf32.f32 %0, %0;" : "+r"(x))

#define CVT_TF32(dst, src) \
    asm volatile("cvt.rna.tf32.f32 %0, %1;" : "=r"(dst) : "r"(src))

// ---------------------------------------------------------------------------
// FMA-only fast tanh (no MUFU)
// ---------------------------------------------------------------------------
__device__ __forceinline__ float fast_tanh(float x) {
    const float C = 7.90531110763549805f;
    float xc = fmaxf(-C, fminf(C, x));
    float x2 = xc * xc;
    float p = -2.76076847742355e-16f;
    p = fmaf(p, x2, 2.00018790482477e-13f);
    p = fmaf(p, x2, -8.60467152213735e-11f);
    p = fmaf(p, x2, 5.12229709037114e-08f);
    p = fmaf(p, x2, 1.48572235717979e-05f);
    p = fmaf(p, x2, 6.37261928875436e-04f);
    p = fmaf(p, x2, 4.89352455891786e-03f);
    p = p * xc;
    float q = 1.19825839466702e-06f;
    q = fmaf(q, x2, 1.18534705686654e-04f);
    q = fmaf(q, x2, 2.26843463243900e-03f);
    q = fmaf(q, x2, 4.89352518554385e-03f);
    float y = __uint_as_float(0x7EF311C3u - __float_as_uint(q));
    y = y * fmaf(-q, y, 2.0f);
    y = y * fmaf(-q, y, 2.0f);
    y = y * fmaf(-q, y, 2.0f);
    return p * y;
}

// ---------------------------------------------------------------------------
// Kernel 0: W_e -> transposed, tf32-rounded fp32  g_Wt[n][k]
// ---------------------------------------------------------------------------
__global__ __launch_bounds__(256) void wconv_kernel(const float* __restrict__ W_attn)
{
    int idx = blockIdx.x * 256 + threadIdx.x;   // 0..262143
    int n = idx & (Hn - 1);                     // coalesced read along n
    int k = idx >> 9;
    uint32_t w = __float_as_uint(W_attn[(size_t)(DHn + k) * Hn + n]);
    uint32_t r;
    CVT_TF32(r, w);
    g_Wt[(size_t)n * Hn + k] = __uint_as_float(r);
}

// ---------------------------------------------------------------------------
// Kernel 1: hpart[d][b] = hidden[b] @ W_h[:,d] + b_attn[d]   (transposed out)
// ---------------------------------------------------------------------------
__global__ __launch_bounds__(512) void hpart_kernel(
    const float* __restrict__ hidden,
    const float* __restrict__ W_attn,
    const float* __restrict__ b_attn)
{
    __shared__ float red[3 * 128];
    int tid = threadIdx.x;
    int dl = tid & 127;
    int kh = tid >> 7;                   // 0..3
    int b = blockIdx.x;
    int d = blockIdx.y * 128 + dl;

    const float* __restrict__ hrow = hidden + b * DHn + kh * 512;
    const float* __restrict__ Wp = W_attn + (size_t)(kh * 512) * Hn + d;
    float acc = 0.0f;
#pragma unroll 8
    for (int k = 0; k < 512; k++) {
        acc = fmaf(hrow[k], Wp[(size_t)k * Hn], acc);
    }
    if (kh > 0) red[(kh - 1) * 128 + dl] = acc;
    __syncthreads();
    if (kh == 0) {
        acc += red[dl] + red[128 + dl] + red[256 + dl] + b_attn[d];
        g_hpart[(size_t)d * Bn + b] = acc;
    }
}

// ---------------------------------------------------------------------------
// Kernel 2: single-pass tf32 mma GEMM + tanh + v-dot
// grid (NBLK, 512); 256 threads (8 warps: 2M x 4N); tile 128x128, KC=32
// 2-stage cp.async, 2 CTAs/SM (64KB smem, <=128 regs)
// ---------------------------------------------------------------------------
__global__ __launch_bounds__(NTHREADS, 2) void main_kernel(
    const float* __restrict__ enc,    // (65536, 512) fp32
    const float* __restrict__ v)
{
    extern __shared__ char smem[];
    const uint32_t sb = smem_u32(smem);
    const int tid = threadIdx.x;
    const int wid = tid >> 5;
    const int lane = tid & 31;
    const int warp_m = wid >> 2;          // 0..1
    const int warp_n = wid & 3;           // 0..3
    const int colbase = blockIdx.x * TN;
    const int rowbase = blockIdx.y * TM;

    float acc[4][4][4];
#pragma unroll
    for (int mt = 0; mt < 4; mt++)
#pragma unroll
        for (int nt = 0; nt < 4; nt++)
#pragma unroll
            for (int q = 0; q < 4; q++) acc[mt][nt][q] = 0.0f;

    // cp.async one K-chunk (A 128x32 f32 + B 128x32 f32) into stage s.
    // Row = 128B (8 x 16B units); swizzle: phys_unit = u ^ (row & 7)
    auto load_chunk = [&](int c, int s) {
        const int kb = c * KC;
        const uint32_t stg = sb + s * STG_BYTES;
#pragma unroll
        for (int j = 0; j < 4; j++) {           // A: 1024 units
            int idx = tid + j * NTHREADS;
            int row = idx >> 3;
            int u = idx & 7;
            uint32_t doff = (uint32_t)(row * 128 + 16 * (u ^ (row & 7)));
            CP16(stg + OFF_A + doff, enc + (size_t)(rowbase + row) * Hn + kb + u * 4);
        }
#pragma unroll
        for (int j = 0; j < 4; j++) {           // B: 1024 units
            int idx = tid + j * NTHREADS;
            int row = idx >> 3;
            int u = idx & 7;
            uint32_t doff = (uint32_t)(row * 128 + 16 * (u ^ (row & 7)));
            CP16(stg + OFF_B + doff, g_Wt + (size_t)(colbase + row) * Hn + kb + u * 4);
        }
    };

    load_chunk(0, 0);
    CP_COMMIT();

    // ldmatrix per-lane addressing (32-bit elements via b16 ldmatrix)
    const int a_r  = ((lane >> 3) & 1) * 8 + (lane & 7);  // row within m16
    const int a_uo = (lane >> 4);                         // 16B-unit offset 0/1
    const int b_r  = ((lane >> 4) & 1) * 8 + (lane & 7);  // n within 16
    const int b_uo = ((lane >> 3) & 1);

    for (int c = 0; c < NCHUNK; c++) {
        if (c + 1 < NCHUNK) {
            load_chunk(c + 1, (c + 1) & 1);
            CP_COMMIT();
            CP_WAIT1();
        } else {
            CP_WAIT0();
        }
        __syncthreads();

        const uint32_t stg = sb + (c & 1) * STG_BYTES;
        const uint32_t sA = stg + OFF_A;
        const uint32_t sB = stg + OFF_B;

#pragma unroll
        for (int ks = 0; ks < 4; ks++) {        // 4 k8-steps per 32-chunk
            const int ub = ks * 2;
            uint32_t afr[4][4], bfr[2][4];
#pragma unroll
            for (int mt = 0; mt < 4; mt++) {
                int row = warp_m * 64 + mt * 16 + a_r;
                uint32_t off = (uint32_t)(row * 128 + 16 * ((ub + a_uo) ^ (row & 7)));
                LDSM4(afr[mt], sA + off);
            }
#pragma unroll
            for (int pr = 0; pr < 2; pr++) {
                int n = warp_n * 32 + pr * 16 + b_r;
                uint32_t off = (uint32_t)(n * 128 + 16 * ((ub + b_uo) ^ (n & 7)));
                LDSM4(bfr[pr], sB + off);
            }
#pragma unroll
            for (int mt = 0; mt < 4; mt++)
#pragma unroll
                for (int q = 0; q < 4; q++)
                    CVT_TF32_IP(afr[mt][q]);
#pragma unroll
            for (int mt = 0; mt < 4; mt++) {
#pragma unroll
                for (int pr = 0; pr < 2; pr++) {
                    MMA_TF32(acc[mt][pr * 2 + 0], afr[mt], bfr[pr][0], bfr[pr][1]);
                    MMA_TF32(acc[mt][pr * 2 + 1], afr[mt], bfr[pr][2], bfr[pr][3]);
                }
            }
        }
        __syncthreads();
    }

    // ---- Epilogue: hp[col][b] (16KB), v (512B), red (128x17 = 8.7KB)
    float* hp_s = (float*)smem;                        // 128*32
    float* v_s  = (float*)(smem + 16384);              // 128
    float* red  = (float*)(smem + 17408);              // 128*17

    for (int i = tid; i < TN * Bn; i += NTHREADS)
        hp_s[i] = g_hpart[(size_t)colbase * Bn + i];
    if (tid < TN) v_s[tid] = v[colbase + tid];
    __syncthreads();

    const int tg = lane & 3;
    const int gid = lane >> 2;
#pragma unroll
    for (int mt = 0; mt < 4; mt++) {
        int r0 = warp_m * 64 + mt * 16 + gid;
        int r1 = r0 + 8;
        int b0 = r0 & 31;
        int b1 = r1 & 31;
        float s0 = 0.0f, s1 = 0.0f;
#pragma unroll
        for (int nt = 0; nt < 4; nt++) {
            int c0 = warp_n * 32 + nt * 8 + tg * 2;
            float v0 = v_s[c0], v1 = v_s[c0 + 1];
            float x00 = acc[mt][nt][0] + hp_s[c0 * 32 + b0];
            float x10 = acc[mt][nt][1] + hp_s[(c0 + 1) * 32 + b0];
            float x01 = acc[mt][nt][2] + hp_s[c0 * 32 + b1];
            float x11 = acc[mt][nt][3] + hp_s[(c0 + 1) * 32 + b1];
            s0 = fmaf(fast_tanh(x00), v0, s0);
            s0 = fmaf(fast_tanh(x10), v1, s0);
            s1 = fmaf(fast_tanh(x01), v0, s1);
            s1 = fmaf(fast_tanh(x11), v1, s1);
        }
        red[r0 * 17 + warp_n * 4 + tg] = s0;
        red[r1 * 17 + warp_n * 4 + tg] = s1;
    }
    __syncthreads();

    if (tid < TM) {
        float s = 0.0f;
#pragma unroll
        for (int j = 0; j < 16; j++) s += red[tid * 17 + j];
        int b = tid & 31;
        int seq = blockIdx.y * (TM / Bn) + (tid >> 5);
        g_partial[blockIdx.x * (Bn * Sn) + b * Sn + seq] = s;
    }
}

// ---------------------------------------------------------------------------
// Kernel 3: sum 4 partials + softmax over s
// ---------------------------------------------------------------------------
__global__ __launch_bounds__(512) void softmax_kernel(float* __restrict__ out)
{
    const int b = blockIdx.x;
    const int tid = threadIdx.x;
    __shared__ float logits[Sn];
    __shared__ float redbuf[512];

    for (int s = tid; s < Sn; s += 512) {
        float t = 0.0f;
#pragma unroll
        for (int j = 0; j < NBLK; j++) t += g_partial[j * (Bn * Sn) + b * Sn + s];
        logits[s] = t;
    }
    __syncthreads();

    float m = -INFINITY;
    for (int s = tid; s < Sn; s += 512) m = fmaxf(m, logits[s]);
    redbuf[tid] = m;
    __syncthreads();
    for (int off = 256; off > 0; off >>= 1) {
        if (tid < off) redbuf[tid] = fmaxf(redbuf[tid], redbuf[tid + off]);
        __syncthreads();
    }
    m = redbuf[0];
    __syncthreads();

    float sum = 0.0f;
    for (int s = tid; s < Sn; s += 512) {
        float e = expf(logits[s] - m);
        logits[s] = e;
        sum += e;
    }
    redbuf[tid] = sum;
    __syncthreads();
    for (int off = 256; off > 0; off >>= 1) {
        if (tid < off) redbuf[tid] += redbuf[tid + off];
        __syncthreads();
    }
    const float inv = 1.0f / redbuf[0];
    __syncthreads();

    for (int s = tid; s < Sn; s += 512) {
        out[b * Sn + s] = logits[s] * inv;
    }
}

// ---------------------------------------------------------------------------
// Launch
// ---------------------------------------------------------------------------
extern "C" void kernel_launch(void* const* d_in, const int* in_sizes, int n_in,
                              void* d_out, int out_size)
{
    const float* hidden = (const float*)d_in[0];
    const float* enc    = (const float*)d_in[1];
    const float* W_attn = (const float*)d_in[2];
    const float* b_attn = (const float*)d_in[3];
    const float* v      = (const float*)d_in[4];
    float* out = (float*)d_out;

    cudaFuncSetAttribute(main_kernel,
                         cudaFuncAttributeMaxDynamicSharedMemorySize, SMEM_TOTAL);

    wconv_kernel<<<1024, 256>>>(W_attn);
    hpart_kernel<<<dim3(Bn, 4), 512>>>(hidden, W_attn, b_attn);
    // grid.x = column blocks so consecutive CTAs share the same A row-tile (L2 dedup)
    main_kernel<<<dim3(NBLK, Mrows / TM), NTHREADS, SMEM_TOTAL>>>(enc, v);
    softmax_kernel<<<Bn, 512>>>(out);
}